// round 2
// baseline (speedup 1.0000x reference)
#include <cuda_runtime.h>
#include <math.h>

// Problem dims
#define Tn 512
#define Bn 64
#define In 512
#define Hn 1024
#define On 512
#define Gn 4096               // 4*H
#define TBn (Tn*Bn)           // 32768

// Persistent recurrence config
#define NCTA 128
#define RPC  32               // W_hh rows per CTA (4 gates x 8 j-columns)
#define NTHR 256
#define HT   128              // h-tile width in k
#define HTS  132              // padded smem stride for h tile
#define GSM_S 34              // padded stride for gate smem [64][34]

// Scratch (device globals; runtime allocation is forbidden)
__device__ float g_pre[(size_t)TBn * Gn];     // 512 MB, reused layer0/layer1
__device__ float g_hseq[(size_t)TBn * Hn];    // hidden sequence (reused per layer)
__device__ float g_h[Bn * Hn];                // current hidden state
__device__ unsigned g_arrive[NCTA] = {};      // grid-barrier arrive flags
__device__ unsigned g_bar_gen = 0;            // grid-barrier generation

typedef unsigned long long u64;

__device__ __forceinline__ void ffma2(u64& d, u64 a, u64 b) {
    asm("fma.rn.f32x2 %0, %1, %2, %0;" : "+l"(d) : "l"(a), "l"(b));
}
__device__ __forceinline__ float2 unpack2(u64 v) {
    float2 r; asm("mov.b64 {%0, %1}, %2;" : "=f"(r.x), "=f"(r.y) : "l"(v)); return r;
}
__device__ __forceinline__ u64 pack2(float x, float y) {
    u64 r; asm("mov.b64 %0, {%1, %2};" : "=l"(r) : "f"(x), "f"(y)); return r;
}
__device__ __forceinline__ u64 d2u(double d) { return __double_as_longlong(d); }

__device__ __forceinline__ float sigf(float x) { return 1.0f / (1.0f + expf(-x)); }

// ---------------------------------------------------------------------------
// Software grid barrier: per-CTA flag slots + checker CTA 0.
// Phases are monotonic across launches/replays (no reset -> no reset race).
// ---------------------------------------------------------------------------
__device__ __forceinline__ void grid_sync(unsigned phase) {
    __syncthreads();
    if (threadIdx.x == 0) {
        __threadfence();
        asm volatile("st.release.gpu.global.u32 [%0], %1;"
                     :: "l"(&g_arrive[blockIdx.x]), "r"(phase) : "memory");
    }
    if (blockIdx.x == 0) {
        if (threadIdx.x < NCTA) {
            unsigned v;
            do {
                asm volatile("ld.acquire.gpu.global.u32 %0, [%1];"
                             : "=r"(v) : "l"(&g_arrive[threadIdx.x]));
            } while (v != phase);
        }
        __syncthreads();
        if (threadIdx.x == 0) {
            __threadfence();
            asm volatile("st.release.gpu.global.u32 [%0], %1;"
                         :: "l"(&g_bar_gen), "r"(phase) : "memory");
        }
    } else if (threadIdx.x == 0) {
        unsigned v;
        do {
            asm volatile("ld.acquire.gpu.global.u32 %0, [%1];"
                         : "=r"(v) : "l"(&g_bar_gen));
        } while (v != phase);
    }
    __syncthreads();
}

// ---------------------------------------------------------------------------
// Persistent LSTM layer: all 512 steps in one launch.
// CTA b owns j-slice j0 = cta*8 across all 4 gates (32 W_hh rows in SMEM).
// Per step: gates_part[64b x 32r] = h @ Wslice^T  (FFMA2, smem-resident W),
// then local cell update for its 512 cells (c lives in registers).
// ---------------------------------------------------------------------------
__global__ void __launch_bounds__(NTHR, 1)
lstm_recur(const float* __restrict__ Whh, const float* __restrict__ pre,
           float* __restrict__ hseq)
{
    extern __shared__ float smem[];
    float4* Wsm = (float4*)smem;              // [256 kg][32 r] float4 = 128 KB
    float*  h_s = smem + 32768;               // [64][HTS] floats (33 KB), reused as gsm
    float*  gsm = h_s;                        // [64][GSM_S] gate partials (8.7 KB)

    const int tid = threadIdx.x;
    const int cta = blockIdx.x;
    const int j0  = cta * 8;
    const int tx  = tid & 15;                 // r-block: local rows 2tx, 2tx+1
    const int ty  = tid >> 4;                 // b-block: batches 4ty..4ty+3

    // Barrier phase base (monotonic across launches; stable at launch time)
    unsigned phase0;
    asm volatile("ld.acquire.gpu.global.u32 %0, [%1];" : "=r"(phase0) : "l"(&g_bar_gen));

    // Load W slice into SMEM, reorganized as Wsm[kg][r] (r = gate*8 + jcol)
    for (int l = 0; l < 32; l++) {
        int r  = l;                           // f = tid + l*256 -> r = l, kg = tid
        int kg = tid;
        int grow = (r >> 3) * Hn + j0 + (r & 7);
        Wsm[kg * 32 + r] = *(const float4*)(Whh + (size_t)grow * Hn + kg * 4);
    }

    // Cell state in registers (fixed thread<->cell mapping)
    const int pb = tid >> 2;                  // batch for pointwise
    const int jj = (tid & 3) * 2;             // j-pair within the 8-column slice
    float c0 = 0.0f, c1 = 0.0f;

    // h-tile loader indices: f = tid + l*256 -> row = f>>5, c4 = f&31
    for (int t = 0; t < Tn; t++) {
        u64 acc[4][2];
#pragma unroll
        for (int i = 0; i < 4; i++) { acc[i][0] = 0ULL; acc[i][1] = 0ULL; }

        // prefetch h tile 0 (g_h valid: memset at t=0, grid_sync otherwise)
        float4 hreg[8];
#pragma unroll
        for (int l = 0; l < 8; l++) {
            int f = tid + l * NTHR;
            hreg[l] = __ldg((const float4*)(g_h + (size_t)(f >> 5) * Hn + (f & 31) * 4));
        }

        for (int kt = 0; kt < Hn / HT; kt++) {
#pragma unroll
            for (int l = 0; l < 8; l++) {
                int f = tid + l * NTHR;
                *(float4*)(h_s + (f >> 5) * HTS + (f & 31) * 4) = hreg[l];
            }
            __syncthreads();
            if (kt + 1 < Hn / HT) {
#pragma unroll
                for (int l = 0; l < 8; l++) {
                    int f = tid + l * NTHR;
                    hreg[l] = __ldg((const float4*)(g_h + (size_t)(f >> 5) * Hn
                                                    + (kt + 1) * HT + (f & 31) * 4));
                }
            }
#pragma unroll 4
            for (int kc = 0; kc < HT / 4; kc++) {
                int kg = kt * (HT / 4) + kc;
                double2 w0 = *(const double2*)(Wsm + kg * 32 + 2 * tx);
                double2 w1 = *(const double2*)(Wsm + kg * 32 + 2 * tx + 1);
                u64 w0a = d2u(w0.x), w0b = d2u(w0.y);
                u64 w1a = d2u(w1.x), w1b = d2u(w1.y);
#pragma unroll
                for (int i = 0; i < 4; i++) {
                    double2 hv = *(const double2*)(h_s + (4 * ty + i) * HTS + kc * 4);
                    u64 ha = d2u(hv.x), hb = d2u(hv.y);
                    ffma2(acc[i][0], ha, w0a); ffma2(acc[i][0], hb, w0b);
                    ffma2(acc[i][1], ha, w1a); ffma2(acc[i][1], hb, w1b);
                }
            }
            __syncthreads();
        }

        // Epilogue: gate partials -> smem [b][local r]
#pragma unroll
        for (int i = 0; i < 4; i++) {
            int b = 4 * ty + i;
            float2 v0 = unpack2(acc[i][0]);
            float2 v1 = unpack2(acc[i][1]);
            *(float2*)(gsm + b * GSM_S + 2 * tx) = make_float2(v0.x + v0.y, v1.x + v1.y);
        }
        __syncthreads();

        // Pointwise cell update: 2 cells per thread (b=pb, j=j0+jj, j0+jj+1)
        {
            const float* gb = gsm + pb * GSM_S;
            float2 ri = *(const float2*)(gb + jj);
            float2 rf = *(const float2*)(gb + 8 + jj);
            float2 rg = *(const float2*)(gb + 16 + jj);
            float2 ro = *(const float2*)(gb + 24 + jj);
            size_t pbase = (size_t)t * ((size_t)Bn * Gn) + (size_t)pb * Gn + j0 + jj;
            float2 qi = *(const float2*)(pre + pbase);
            float2 qf = *(const float2*)(pre + pbase + Hn);
            float2 qg = *(const float2*)(pre + pbase + 2 * Hn);
            float2 qo = *(const float2*)(pre + pbase + 3 * Hn);

            float i0 = sigf(ri.x + qi.x), i1 = sigf(ri.y + qi.y);
            float f0 = sigf(rf.x + qf.x), f1 = sigf(rf.y + qf.y);
            float g0 = tanhf(rg.x + qg.x), g1 = tanhf(rg.y + qg.y);
            float o0 = sigf(ro.x + qo.x), o1 = sigf(ro.y + qo.y);
            c0 = f0 * c0 + i0 * g0;
            c1 = f1 * c1 + i1 * g1;
            float h0 = o0 * tanhf(c0);
            float h1 = o1 * tanhf(c1);

            int hidx = pb * Hn + j0 + jj;
            *(float2*)(g_h + hidx) = make_float2(h0, h1);
            *(float2*)(hseq + (size_t)t * Bn * Hn + hidx) = make_float2(h0, h1);
        }

        grid_sync(phase0 + t + 1);   // h ready for next step (and gsm reuse safe)
    }
}

// ---------------------------------------------------------------------------
// C[M,N] = A[M,K] @ W[N,K]^T + b0[N] (+ b1[N] if non-null). FFMA2 SIMT GEMM.
// ---------------------------------------------------------------------------
template<int BM, int BN, int BK, int TM, int TN>
__global__ void __launch_bounds__((BM/TM)*(BN/TN))
gemm_bias(const float* __restrict__ A, const float* __restrict__ W,
          const float* __restrict__ b0, const float* __restrict__ b1,
          float* __restrict__ C, int M, int N, int K)
{
    constexpr int NT = (BM/TM)*(BN/TN);
    constexpr int TX = BN/TN;
    __shared__ float As[BK][BM];
    __shared__ float Ws[BK][BN];
    const int tid = threadIdx.x;
    const int tx = tid % TX, ty = tid / TX;
    const int m0 = blockIdx.y * BM, n0 = blockIdx.x * BN;

    u64 acc[TM][TN/2];
#pragma unroll
    for (int i = 0; i < TM; i++)
#pragma unroll
        for (int j = 0; j < TN/2; j++) acc[i][j] = 0ULL;

    for (int k0 = 0; k0 < K; k0 += BK) {
#pragma unroll
        for (int l = 0; l < BM*BK/4/NT; l++) {
            int f = tid + l*NT;
            int row = f / (BK/4), cv = f % (BK/4);
            float4 v = *reinterpret_cast<const float4*>(A + (size_t)(m0+row)*K + k0 + cv*4);
            As[cv*4+0][row] = v.x; As[cv*4+1][row] = v.y;
            As[cv*4+2][row] = v.z; As[cv*4+3][row] = v.w;
        }
#pragma unroll
        for (int l = 0; l < BN*BK/4/NT; l++) {
            int f = tid + l*NT;
            int row = f / (BK/4), cv = f % (BK/4);
            float4 v = *reinterpret_cast<const float4*>(W + (size_t)(n0+row)*K + k0 + cv*4);
            Ws[cv*4+0][row] = v.x; Ws[cv*4+1][row] = v.y;
            Ws[cv*4+2][row] = v.z; Ws[cv*4+3][row] = v.w;
        }
        __syncthreads();
#pragma unroll
        for (int kk = 0; kk < BK; kk++) {
            float a[TM];
            u64 w[TN/2];
#pragma unroll
            for (int i = 0; i < TM; i += 4) {
                float4 v = *reinterpret_cast<const float4*>(&As[kk][ty*TM + i]);
                a[i] = v.x; a[i+1] = v.y; a[i+2] = v.z; a[i+3] = v.w;
            }
#pragma unroll
            for (int j = 0; j < TN/2; j++)
                w[j] = *reinterpret_cast<const u64*>(&Ws[kk][tx*TN + 2*j]);
#pragma unroll
            for (int i = 0; i < TM; i++) {
                u64 ad = pack2(a[i], a[i]);
#pragma unroll
                for (int j = 0; j < TN/2; j++) ffma2(acc[i][j], ad, w[j]);
            }
        }
        __syncthreads();
    }

    float bias[TN];
#pragma unroll
    for (int j = 0; j < TN; j++) {
        int n = n0 + tx*TN + j;
        bias[j] = b0[n] + (b1 ? b1[n] : 0.0f);
    }
#pragma unroll
    for (int i = 0; i < TM; i++) {
        size_t base = (size_t)(m0 + ty*TM + i)*N + n0 + tx*TN;
#pragma unroll
        for (int j = 0; j < TN/2; j++) {
            float2 v = unpack2(acc[i][j]);
            C[base + 2*j]   = v.x + bias[2*j];
            C[base + 2*j+1] = v.y + bias[2*j+1];
        }
    }
}

// ---------------------------------------------------------------------------
extern "C" void kernel_launch(void* const* d_in, const int* in_sizes, int n_in,
                              void* d_out, int out_size)
{
    const float* x    = (const float*)d_in[0];
    const float* Wih0 = (const float*)d_in[1];
    const float* Whh0 = (const float*)d_in[2];
    const float* bih0 = (const float*)d_in[3];
    const float* bhh0 = (const float*)d_in[4];
    const float* Wih1 = (const float*)d_in[5];
    const float* Whh1 = (const float*)d_in[6];
    const float* bih1 = (const float*)d_in[7];
    const float* bhh1 = (const float*)d_in[8];
    const float* Wout = (const float*)d_in[9];
    const float* bout = (const float*)d_in[10];
    float* out = (float*)d_out;

    float *pre, *hs, *h;
    cudaGetSymbolAddress((void**)&pre, g_pre);
    cudaGetSymbolAddress((void**)&hs,  g_hseq);
    cudaGetSymbolAddress((void**)&h,   g_h);

    const int SMEM_RECUR = 131072 + 64 * HTS * 4;   // W slice + h tile
    cudaFuncSetAttribute(lstm_recur, cudaFuncAttributeMaxDynamicSharedMemorySize,
                         SMEM_RECUR);

    // ---- Layer 0 ----
    gemm_bias<128,128,16,8,8><<<dim3(Gn/128, TBn/128), 256>>>(
        x, Wih0, bih0, bhh0, pre, TBn, Gn, In);
    cudaMemsetAsync(h, 0, sizeof(float)*Bn*Hn);
    lstm_recur<<<NCTA, NTHR, SMEM_RECUR>>>(Whh0, pre, hs);

    // ---- Layer 1 ----
    gemm_bias<128,128,16,8,8><<<dim3(Gn/128, TBn/128), 256>>>(
        hs, Wih1, bih1, bhh1, pre, TBn, Gn, Hn);
    cudaMemsetAsync(h, 0, sizeof(float)*Bn*Hn);
    lstm_recur<<<NCTA, NTHR, SMEM_RECUR>>>(Whh1, pre, hs);

    // ---- Output projection ----
    gemm_bias<128,128,16,8,8><<<dim3(On/128, TBn/128), 256>>>(
        hs, Wout, bout, nullptr, out, TBn, On, Hn);
}